// round 9
// baseline (speedup 1.0000x reference)
#include <cuda_runtime.h>
#include <stdint.h>

#define BB 8
#define SS 2047
#define RT 1162
#define ROWS (BB * SS)
#define NEGF (-1e9f)

// FINAL inclusive prefix per (b, j), padded to 2048 rows per batch.
// words 0..4 = instrument-present bitset (129 bits),
// word 5 = key_sign:  flag<<31 | j<<8 | value   (max selects latest; value inline)
// word 6 = time_sign: same encoding
// word 7 = tempo:     j<<8 | value, element j==0 always seeds its value
//          (matches jnp.argmax-of-zeros -> song[b,0,feat] semantics).
__device__ uint32_t g_prefix[(size_t)BB * 2048 * 8];

__constant__ int c_num[12] = {1, 2, 3, 4, 5, 6, 7, 8, 9, 10, 12, 16};

__device__ __forceinline__ uint32_t pmax(uint32_t a, uint32_t b) { return a > b ? a : b; }

struct St {
    uint32_t w[8];
};

__device__ __forceinline__ void st_zero(St& s) {
#pragma unroll
    for (int k = 0; k < 8; ++k) s.w[k] = 0;
}
__device__ __forceinline__ void st_comb(St& a, const St& b) {   // a = a ⊕ b (b later)
    a.w[0] |= b.w[0]; a.w[1] |= b.w[1]; a.w[2] |= b.w[2];
    a.w[3] |= b.w[3]; a.w[4] |= b.w[4];
    a.w[5] = pmax(a.w[5], b.w[5]);
    a.w[6] = pmax(a.w[6], b.w[6]);
    a.w[7] = pmax(a.w[7], b.w[7]);
}

// Build element state for song row j (valid j only).
__device__ __forceinline__ void st_elem(St& s, const int* __restrict__ e, int j) {
    st_zero(s);
    int ty = e[0];          // all loads issued together (MLP)
    int v6 = e[6];
    int v8 = e[8];
    int v9 = e[9];
    int v10 = e[10];
    if (ty == 1) {
        s.w[v6 >> 5] |= 1u << (v6 & 31);
    } else if (ty == 4) {
        s.w[5] = 0x80000000u | ((uint32_t)j << 8) | (uint32_t)v8;
    } else if (ty == 5) {
        s.w[6] = 0x80000000u | ((uint32_t)j << 8) | (uint32_t)v9;
    } else if (ty == 6) {
        s.w[7] = ((uint32_t)j << 8) | (uint32_t)v10;
    }
    if (j == 0) {           // seed: no-match default is index 0 -> its value
        s.w[5] = pmax(s.w[5], (uint32_t)v8);
        s.w[6] = pmax(s.w[6], (uint32_t)v9);
        s.w[7] = pmax(s.w[7], (uint32_t)v10);
    }
}

// One fused scan: 8 blocks (one per batch) x 1024 threads x 2 elements.
__global__ __launch_bounds__(1024) void scan_kernel(const int* __restrict__ song) {
    int b = blockIdx.x;
    int tid = threadIdx.x, lane = tid & 31, warp = tid >> 5;
    int j0 = tid * 2;
    const int* sb = song + (size_t)b * SS * 11;

    St S0, S1;
    st_elem(S0, sb + (size_t)j0 * 11, j0);
    bool has1 = (j0 + 1) < SS;
    if (has1) st_elem(S1, sb + (size_t)(j0 + 1) * 11, j0 + 1);
    else st_zero(S1);

    St T = S0;                // thread aggregate
    st_comb(T, S1);

    // warp-inclusive shuffle scan on T
#pragma unroll
    for (int d = 1; d < 32; d <<= 1) {
        St o;
#pragma unroll
        for (int k = 0; k < 8; ++k) o.w[k] = __shfl_up_sync(0xffffffffu, T.w[k], d);
        if (lane >= d) {
            T.w[0] |= o.w[0]; T.w[1] |= o.w[1]; T.w[2] |= o.w[2];
            T.w[3] |= o.w[3]; T.w[4] |= o.w[4];
            T.w[5] = pmax(T.w[5], o.w[5]);
            T.w[6] = pmax(T.w[6], o.w[6]);
            T.w[7] = pmax(T.w[7], o.w[7]);
        }
    }

    __shared__ uint32_t sagg[32][8];
    if (lane == 31) {
#pragma unroll
        for (int k = 0; k < 8; ++k) sagg[warp][k] = T.w[k];
    }
    __syncthreads();

    // warp 0 scans the 32 warp aggregates (inclusive), writes back
    if (warp == 0) {
        St A;
#pragma unroll
        for (int k = 0; k < 8; ++k) A.w[k] = sagg[lane][k];
#pragma unroll
        for (int d = 1; d < 32; d <<= 1) {
            St o;
#pragma unroll
            for (int k = 0; k < 8; ++k) o.w[k] = __shfl_up_sync(0xffffffffu, A.w[k], d);
            if (lane >= d) {
                A.w[0] |= o.w[0]; A.w[1] |= o.w[1]; A.w[2] |= o.w[2];
                A.w[3] |= o.w[3]; A.w[4] |= o.w[4];
                A.w[5] = pmax(A.w[5], o.w[5]);
                A.w[6] = pmax(A.w[6], o.w[6]);
                A.w[7] = pmax(A.w[7], o.w[7]);
            }
        }
#pragma unroll
        for (int k = 0; k < 8; ++k) sagg[lane][k] = A.w[k];
    }
    __syncthreads();

    // exclusive thread prefix = shfl_up(T,1) ⊕ warp carry
    St E;
#pragma unroll
    for (int k = 0; k < 8; ++k) E.w[k] = __shfl_up_sync(0xffffffffu, T.w[k], 1);
    if (lane == 0) st_zero(E);
    if (warp > 0) {
        St C;
#pragma unroll
        for (int k = 0; k < 8; ++k) C.w[k] = sagg[warp - 1][k];
        st_comb(E, C);
    }

    // per-element inclusive prefixes, store
    st_comb(E, S0);   // prefix at j0
    {
        uint4* dst = (uint4*)&g_prefix[((size_t)b * 2048 + j0) * 8];
        dst[0] = make_uint4(E.w[0], E.w[1], E.w[2], E.w[3]);
        dst[1] = make_uint4(E.w[4], E.w[5], E.w[6], E.w[7]);
    }
    if (has1) {
        st_comb(E, S1);   // prefix at j0+1
        uint4* dst = (uint4*)&g_prefix[((size_t)b * 2048 + j0 + 1) * 8];
        dst[0] = make_uint4(E.w[0], E.w[1], E.w[2], E.w[3]);
        dst[1] = make_uint4(E.w[4], E.w[5], E.w[6], E.w[7]);
    }
}

// Warp per row: prefix loads issued early, argmax overlaps them, then copy +
// sparse overwrites. No block barrier.
__global__ __launch_bounds__(256) void apply_kernel(const int* __restrict__ song,
                                                    const int* __restrict__ chosen,
                                                    const float* __restrict__ scores,
                                                    float* __restrict__ out) {
    int warp = threadIdx.x >> 5;
    int lane = threadIdx.x & 31;
    int row = blockIdx.x * 8 + warp;      // grid = 2047 -> 16376 rows exactly
    int b = row / SS;
    int i = row - b * SS;
    const float* srow = scores + (size_t)row * RT;
    float* orow = out + (size_t)row * RT;

    __shared__ int sp_all[8][16];
    int* sp = sp_all[warp];

    // --- lane 0: issue all scalar loads FIRST (independent of the argmax) ---
    uint4 p0, p1;
    int sm1 = 0, sb2 = 0, sp3 = 0, tcho = 0;
    if (lane == 0) {
        int jj = (i + 1 < SS) ? i + 1 : SS - 1;
        const uint4* PL = (const uint4*)&g_prefix[((size_t)b * 2048 + jj) * 8];
        p0 = PL[0]; p1 = PL[1];
        const int* si = song + (size_t)row * 11;
        sm1 = si[1]; sb2 = si[2]; sp3 = si[3];
        tcho = chosen[row];
    }

    // --- measure argmax over scores[0:256] (first-index tiebreak = jnp.argmax) ---
    float bv = srow[lane];
    int bi = lane;
#pragma unroll
    for (int k = 1; k < 8; ++k) {
        float v = srow[lane + 32 * k];
        if (v > bv) { bv = v; bi = lane + 32 * k; }
    }
#pragma unroll
    for (int d = 16; d; d >>= 1) {
        float ov = __shfl_down_sync(0xffffffffu, bv, d);
        int oi = __shfl_down_sync(0xffffffffu, bi, d);
        if (ov > bv || (ov == bv && oi < bi)) { bv = ov; bi = oi; }
    }
    int pred_m = bi;   // valid on lane 0

    // --- beat argmax over scores[256:272] ---
    float bb = srow[256 + (lane & 15)];
    int bj = lane & 15;
#pragma unroll
    for (int d = 8; d; d >>= 1) {
        float ov = __shfl_down_sync(0xffffffffu, bb, d, 16);
        int oj = __shfl_down_sync(0xffffffffu, bj, d, 16);
        if (ov > bb || (ov == bb && oj < bj)) { bb = ov; bj = oj; }
    }
    int pred_b = bj;   // valid on lane 0

    if (lane == 0) {
        uint32_t w0 = p0.x, w1 = p0.y, w2 = p0.z, w3 = p0.w, w4 = p1.x;
        uint32_t wk = p1.y, wt = p1.z, wp = p1.w;

        int last_ks = (int)(wk & 0xffu);
        int last_ts = (int)(wt & 0xffu);
        int last_tp = (int)(wp & 0xffu);
        bool has_ks = (wk >> 31) != 0;
        bool has_ts = (wt >> 31) != 0;
        int max_beat = c_num[last_ts % 12];

        bool c1f = (pred_m == sm1);
        int min_beat = c1f ? sb2 : 0;
        bool c2f = c1f && (pred_b == min_beat);
        int min_pos = c2f ? sp3 : 0;
        int min_m46 = (sb2 == 0 && sp3 == 0) ? sm1 : sm1 + 1;
        bool has_inst = (w0 | w1 | w2 | w3 | w4) != 0;
        bool is3 = (tcho == 3);

        sp[0] = (int)w0; sp[1] = (int)w1; sp[2] = (int)w2;
        sp[3] = (int)w3; sp[4] = (int)w4;
        sp[5] = is3 ? sm1 : ((tcho >= 4 && tcho <= 6) ? min_m46 : 0);
        sp[6] = is3 ? min_beat : 0;
        sp[7] = is3 ? max_beat : 16;
        sp[8] = is3 ? min_pos : 0;
        sp[9] = is3 ? 1 : ((tcho == 1 && has_inst) ? 2 : 0);
        sp[10] = is3 ? 1 : ((tcho == 4 && has_ks) ? 2 : 0);
        sp[11] = last_ks;
        sp[12] = is3 ? 1 : ((tcho == 5 && has_ts) ? 2 : 0);
        sp[13] = last_ts;
        sp[14] = is3 ? 1 : ((tcho == 6) ? 2 : 0);
        sp[15] = last_tp;
    }

    // --- float4 copy (row byte offset = row*4648; 16B-aligned iff row even) ---
    if ((row & 1) == 0) {
        const float4* s4 = (const float4*)srow;
        float4* o4 = (float4*)orow;
#pragma unroll
        for (int p = lane; p < 290; p += 32) o4[p] = s4[p];    // floats 0..1159
        if (lane == 0) *(float2*)(orow + 1160) = *(const float2*)(srow + 1160);
    } else {
        const float4* s4 = (const float4*)(srow + 2);
        float4* o4 = (float4*)(orow + 2);
#pragma unroll
        for (int p = lane; p < 290; p += 32) o4[p] = s4[p];    // floats 2..1161
        if (lane == 0) *(float2*)orow = *(const float2*)srow;
    }
    __syncwarp();

    // --- sparse overwrites (lane-strided) ---
    int mth = sp[5], blo = sp[6], bhi = sp[7], pth = sp[8];
    int imode = sp[9], kmode = sp[10], kval = sp[11];
    int tsm = sp[12], tsv = sp[13], tpm = sp[14], tpv = sp[15];

    for (int c = lane; c < mth; c += 32) orow[c] = NEGF;                 // measure
    if (lane < 16 && (lane < blo || lane >= bhi)) orow[256 + lane] = NEGF;  // beat
    for (int p = lane; p < pth; p += 32) orow[272 + p] = NEGF;           // position
    if (imode) {                                                          // instrument
#pragma unroll
        for (int k = 0; k < 5; ++k) {
            int ci = lane + 32 * k;
            if (ci < 129) {
                bool pres = ((uint32_t)sp[k] >> lane) & 1u;
                bool masked = (imode == 1) ? !pres : pres;
                if (masked) orow[784 + ci] = NEGF;
            }
        }
    }
    if (kmode && lane < 24) {                                             // key_sign
        bool masked = (kmode == 1) ? (lane != kval) : (lane == kval);
        if (masked) orow[1041 + lane] = NEGF;
    }
    if (tsm) {                                                            // time_sign
#pragma unroll
        for (int k = 0; k < 2; ++k) {
            int ct = lane + 32 * k;
            if (ct < 48) {
                bool masked = (tsm == 1) ? (ct != tsv) : (ct == tsv);
                if (masked) orow[1065 + ct] = NEGF;
            }
        }
    }
    if (tpm) {                                                            // tempo
#pragma unroll
        for (int k = 0; k < 2; ++k) {
            int cp = lane + 32 * k;
            if (cp < 49) {
                bool masked = (tpm == 1) ? (cp != tpv) : (cp == tpv);
                if (masked) orow[1113 + cp] = NEGF;
            }
        }
    }
}

extern "C" void kernel_launch(void* const* d_in, const int* in_sizes, int n_in,
                              void* d_out, int out_size) {
    const int* song = (const int*)d_in[0];
    const int* chosen = (const int*)d_in[1];
    const float* scores = (const float*)d_in[2];
    float* out = (float*)d_out;

    scan_kernel<<<BB, 1024>>>(song);
    apply_kernel<<<ROWS / 8, 256>>>(song, chosen, scores, out);
}